// round 13
// baseline (speedup 1.0000x reference)
#include <cuda_runtime.h>
#include <cuda_bf16.h>
#include <cstdint>
#include <math.h>

// Problem constants
static constexpr int D_MODEL = 1024;
static constexpr int NH      = 16;
static constexpr int DKH     = 64;
static constexpr int SEQ     = 2048;
static constexpr int BATCH   = 4;
static constexpr int MROWS   = BATCH * SEQ;               // 8192
static constexpr int QKV_ELEMS = BATCH * NH * SEQ * DKH;  // 8388608
static constexpr size_t AMAT = (size_t)MROWS * D_MODEL;   // 8388608

// Scratch (device globals: allocation-free rule)
// Pre-split activations for QKV GEMMs: [3][m][k] bf16 hi/lo
__device__ __nv_bfloat16 g_Ah[3 * AMAT], g_Al[3 * AMAT];
// Attention output, pre-split for the out GEMM: [B,S,H*DK] bf16 hi/lo
__device__ __nv_bfloat16 g_Oh[AMAT], g_Ol[AMAT];
// Split-bf16 Q/K in [B,H,S,DK]; V transposed in [B,H,DK,S]
__device__ __nv_bfloat16 g_Qh[QKV_ELEMS], g_Ql[QKV_ELEMS];
__device__ __nv_bfloat16 g_Kh[QKV_ELEMS], g_Kl[QKV_ELEMS];
__device__ __nv_bfloat16 g_Vth[QKV_ELEMS], g_Vtl[QKV_ELEMS];
// Pre-transposed + bf16-split weights: Wt[n][k] for each of 4 matrices
__device__ __nv_bfloat16 g_Wthi[4 * D_MODEL * D_MODEL];
__device__ __nv_bfloat16 g_Wtlo[4 * D_MODEL * D_MODEL];

// ===========================================================================
// Helpers (sm_100 base target: mma.sync + cp.async + ldmatrix; NO tcgen05)
// ===========================================================================
__device__ __forceinline__ uint32_t smem_u32(const void* p) {
    uint32_t a;
    asm("{ .reg .u64 t; cvta.to.shared.u64 t, %1; cvt.u32.u64 %0, t; }"
        : "=r"(a) : "l"(p));
    return a;
}

__device__ __forceinline__ void cp16(uint32_t dst, const void* src) {
    asm volatile("cp.async.cg.shared.global [%0], [%1], 16;" :: "r"(dst), "l"(src));
}
#define CP_COMMIT() asm volatile("cp.async.commit_group;" ::: "memory")
#define CP_WAIT0()  asm volatile("cp.async.wait_group 0;" ::: "memory")
#define CP_WAIT1()  asm volatile("cp.async.wait_group 1;" ::: "memory")

// m16n8k16 bf16 MMA, fp32 accumulate
__device__ __forceinline__ void mma_bf16(float* c, const uint32_t* a,
                                         uint32_t b0, uint32_t b1) {
    asm volatile(
        "mma.sync.aligned.m16n8k16.row.col.f32.bf16.bf16.f32 "
        "{%0,%1,%2,%3}, {%4,%5,%6,%7}, {%8,%9}, {%0,%1,%2,%3};"
        : "+f"(c[0]), "+f"(c[1]), "+f"(c[2]), "+f"(c[3])
        : "r"(a[0]), "r"(a[1]), "r"(a[2]), "r"(a[3]), "r"(b0), "r"(b1));
}

// ldmatrix x4: lanes 0-7/8-15/16-23/24-31 address matrices 0/1/2/3
__device__ __forceinline__ void ldmx4(uint32_t* r, uint32_t addr) {
    asm volatile("ldmatrix.sync.aligned.m8n8.x4.shared.b16 {%0,%1,%2,%3}, [%4];"
        : "=r"(r[0]), "=r"(r[1]), "=r"(r[2]), "=r"(r[3]) : "r"(addr));
}

__device__ __forceinline__ uint32_t pack_bf16x2(__nv_bfloat16 lo, __nv_bfloat16 hi) {
    return (uint32_t)__bfloat16_as_ushort(lo) |
           ((uint32_t)__bfloat16_as_ushort(hi) << 16);
}

__device__ __forceinline__ void split4(float4 f, uint2& hi, uint2& lo) {
    const __nv_bfloat16 h0 = __float2bfloat16(f.x), h1 = __float2bfloat16(f.y);
    const __nv_bfloat16 h2 = __float2bfloat16(f.z), h3 = __float2bfloat16(f.w);
    hi.x = pack_bf16x2(h0, h1);
    hi.y = pack_bf16x2(h2, h3);
    lo.x = pack_bf16x2(__float2bfloat16(f.x - __bfloat162float(h0)),
                       __float2bfloat16(f.y - __bfloat162float(h1)));
    lo.y = pack_bf16x2(__float2bfloat16(f.z - __bfloat162float(h2)),
                       __float2bfloat16(f.w - __bfloat162float(h3)));
}

// Split two fp32 values into packed hi / packed lo bf16x2
__device__ __forceinline__ void split2(float v0, float v1, uint32_t& hi, uint32_t& lo) {
    const __nv_bfloat16 h0 = __float2bfloat16(v0), h1 = __float2bfloat16(v1);
    hi = pack_bf16x2(h0, h1);
    lo = pack_bf16x2(__float2bfloat16(v0 - __bfloat162float(h0)),
                     __float2bfloat16(v1 - __bfloat162float(h1)));
}

// ===========================================================================
// Activation pre-split: fp32 [m][k] -> bf16 hi/lo [m][k]  (q, k, v inputs)
// ===========================================================================
__global__ void __launch_bounds__(256)
asplit_kernel(const float* __restrict__ q, const float* __restrict__ k,
              const float* __restrict__ v)
{
    const int z = blockIdx.y;
    const float* X = (z == 0) ? q : (z == 1) ? k : v;
    __nv_bfloat16* H = g_Ah + (size_t)z * AMAT;
    __nv_bfloat16* L = g_Al + (size_t)z * AMAT;
    const size_t i4 = (size_t)blockIdx.x * 256 + threadIdx.x;  // float4 index
    const float4 f = *(const float4*)(X + i4 * 4);
    uint2 hi, lo;
    split4(f, hi, lo);
    *(uint2*)(H + i4 * 4) = hi;
    *(uint2*)(L + i4 * 4) = lo;
}

// ===========================================================================
// Weight conversion: W[k][n] fp32  ->  Wt_hi/lo[n][k] bf16 (transposed + split)
// ===========================================================================
__global__ void __launch_bounds__(256)
wconv_kernel(const float* __restrict__ W0, const float* __restrict__ W1,
             const float* __restrict__ W2, const float* __restrict__ W3)
{
    const int z = blockIdx.z;
    const float* W = (z == 0) ? W0 : (z == 1) ? W1 : (z == 2) ? W2 : W3;
    __shared__ float t[32][33];
    const int tx = threadIdx.x & 31;
    const int ty = threadIdx.x >> 5;
    const int kb = blockIdx.y * 32, nb = blockIdx.x * 32;
#pragma unroll
    for (int i = 0; i < 4; ++i)
        t[ty + i * 8][tx] = W[(size_t)(kb + ty + i * 8) * D_MODEL + nb + tx];
    __syncthreads();
    __nv_bfloat16* oh = g_Wthi + (size_t)z * D_MODEL * D_MODEL;
    __nv_bfloat16* ol = g_Wtlo + (size_t)z * D_MODEL * D_MODEL;
#pragma unroll
    for (int i = 0; i < 4; ++i) {
        const int n = nb + ty + i * 8, k = kb + tx;
        const float v = t[tx][ty + i * 8];
        const __nv_bfloat16 h = __float2bfloat16(v);
        oh[(size_t)n * D_MODEL + k] = h;
        ol[(size_t)n * D_MODEL + k] = __float2bfloat16(v - __bfloat162float(h));
    }
}

// ===========================================================================
// Split-bf16 mma.sync GEMM; A pre-split (cp.async), ldmatrix loads,
// R10 MMA ordering (proven fastest). mode 0: fp32 dense + bias;
// mode 1: split bf16 -> [B,H,S,DK]; mode 2: split bf16 -> [B,H,DK,S].
// __launch_bounds__(256, 2): 2 CTAs/SM.
// ===========================================================================
static constexpr int SA       = 40;
static constexpr int AB_BYTES = 128 * SA * 2;
static constexpr int OFF_AH = 0;
static constexpr int OFF_AL = AB_BYTES;
static constexpr int OFF_BH = 2 * AB_BYTES;
static constexpr int OFF_BL = 3 * AB_BYTES;
static constexpr int STAGE  = 4 * AB_BYTES;
static constexpr int MMA_SMEM = 2 * STAGE;             // 81920 B

__device__ __forceinline__ void mma_gemm_body(
    const __nv_bfloat16* __restrict__ Ahi,        // [8192][1024] bf16 hi
    const __nv_bfloat16* __restrict__ Alo,        // [8192][1024] bf16 lo
    const __nv_bfloat16* __restrict__ Wth,
    const __nv_bfloat16* __restrict__ Wtl,
    const float* __restrict__ bias,
    float* __restrict__ dstF,
    __nv_bfloat16* __restrict__ dstHi, __nv_bfloat16* __restrict__ dstLo,
    int mode, int bx, int by)
{
    extern __shared__ char sm[];
    const uint32_t smb = smem_u32(sm);

    const int tid    = threadIdx.x;
    const int lane   = tid & 31;
    const int wid    = tid >> 5;
    const int warp_m = wid >> 2;
    const int warp_n = wid & 3;
    const int r0     = lane >> 2;
    const int kc     = (lane & 3) * 2;
    const uint32_t lr  = lane & 7;     // ldmatrix row within 8x8
    const uint32_t sel = lane >> 3;    // ldmatrix matrix select

    const __nv_bfloat16* Ah_row = Ahi + (size_t)(by * 128) * D_MODEL;
    const __nv_bfloat16* Al_row = Alo + (size_t)(by * 128) * D_MODEL;
    const __nv_bfloat16* Bh_row = Wth + (size_t)(bx * 128) * D_MODEL;
    const __nv_bfloat16* Bl_row = Wtl + (size_t)(bx * 128) * D_MODEL;

    float acc[4][4][4];
#pragma unroll
    for (int i = 0; i < 4; ++i)
#pragma unroll
        for (int j = 0; j < 4; ++j)
#pragma unroll
            for (int q = 0; q < 4; ++q) acc[i][j][q] = 0.0f;

    // Load whole chunk (A hi/lo + B hi/lo) via cp.async; one commit group.
    auto issue_AB = [&](int c, int s) {
        const int k0 = c * 32;
        const uint32_t sb = smb + s * STAGE;
#pragma unroll
        for (int i = 0; i < 2; ++i) {
            const int lin = tid + 256 * i;      // 0..511
            const int r   = lin >> 2;           // 0..127
            const int k8  = (lin & 3) * 8;      // 0,8,16,24
            const uint32_t so = (uint32_t)(r * SA + k8) * 2;
            cp16(sb + OFF_AH + so, Ah_row + (size_t)r * D_MODEL + k0 + k8);
            cp16(sb + OFF_AL + so, Al_row + (size_t)r * D_MODEL + k0 + k8);
            cp16(sb + OFF_BH + so, Bh_row + (size_t)r * D_MODEL + k0 + k8);
            cp16(sb + OFF_BL + so, Bl_row + (size_t)r * D_MODEL + k0 + k8);
        }
        CP_COMMIT();
    };

    issue_AB(0, 0);
    CP_WAIT0();
    __syncthreads();

    // ldmatrix lane-offsets (within tile, in bf16 elements):
    // A: row = lr + (sel&1)*8, col = (sel>>1)*8
    // B: row = lr + (sel>>1)*8, col = (sel&1)*8
    const uint32_t a_lane_off = ((lr + (sel & 1) * 8) * SA + (sel >> 1) * 8) * 2;
    const uint32_t b_lane_off = ((lr + (sel >> 1) * 8) * SA + (sel & 1) * 8) * 2;

    for (int c = 0; c < 32; ++c) {
        const int s = c & 1;
        if (c + 1 < 32) issue_AB(c + 1, s ^ 1);

        const uint32_t stg = smb + s * STAGE;

#pragma unroll
        for (int ks = 0; ks < 2; ++ks) {
            const uint32_t k0b = (uint32_t)(ks * 16) * 2;  // bytes
            uint32_t ah[4][4], al[4][4];
#pragma unroll
            for (int mf = 0; mf < 4; ++mf) {
                const uint32_t ao = a_lane_off + k0b +
                    (uint32_t)((warp_m * 64 + mf * 16) * SA) * 2;
                ldmx4(ah[mf], stg + OFF_AH + ao);
                ldmx4(al[mf], stg + OFF_AL + ao);
            }
#pragma unroll
            for (int nfp = 0; nfp < 2; ++nfp) {
                uint32_t bh[4], bl[4];
                const uint32_t bo = b_lane_off + k0b +
                    (uint32_t)((warp_n * 32 + nfp * 16) * SA) * 2;
                ldmx4(bh, stg + OFF_BH + bo);
                ldmx4(bl, stg + OFF_BL + bo);
#pragma unroll
                for (int mf = 0; mf < 4; ++mf) {
                    mma_bf16(acc[mf][2 * nfp],     ah[mf], bh[0], bh[1]);
                    mma_bf16(acc[mf][2 * nfp],     al[mf], bh[0], bh[1]);
                    mma_bf16(acc[mf][2 * nfp],     ah[mf], bl[0], bl[1]);
                    mma_bf16(acc[mf][2 * nfp + 1], ah[mf], bh[2], bh[3]);
                    mma_bf16(acc[mf][2 * nfp + 1], al[mf], bh[2], bh[3]);
                    mma_bf16(acc[mf][2 * nfp + 1], ah[mf], bl[2], bl[3]);
                }
            }
        }

        if (c + 1 < 32) {
            CP_WAIT0();
            __syncthreads();
        }
    }

    // ---- epilogue -------------------------------------------------------
#pragma unroll
    for (int mf = 0; mf < 4; ++mf) {
        const int m0 = by * 128 + warp_m * 64 + mf * 16 + r0;
#pragma unroll
        for (int nf = 0; nf < 4; ++nf) {
            const int n = bx * 128 + warp_n * 32 + nf * 8 + kc;
            const float b0 = bias[n], b1 = bias[n + 1];
            const float* c = acc[mf][nf];
            const float v0 = c[0] + b0, v1 = c[1] + b1;
            const float v2 = c[2] + b0, v3 = c[3] + b1;
            if (mode == 0) {
                *(float2*)(dstF + (size_t)m0 * D_MODEL + n) = make_float2(v0, v1);
                *(float2*)(dstF + (size_t)(m0 + 8) * D_MODEL + n) = make_float2(v2, v3);
            } else {
                const int b = m0 >> 11;
                const int srow = m0 & (SEQ - 1);
                const int h = n >> 6;
                const int dk = n & (DKH - 1);
                if (mode == 1) {
                    const size_t base = ((size_t)(b * NH + h) * SEQ + srow) * DKH + dk;
                    uint32_t hi, lo;
                    split2(v0, v1, hi, lo);
                    *(uint32_t*)(dstHi + base) = hi;
                    *(uint32_t*)(dstLo + base) = lo;
                    split2(v2, v3, hi, lo);
                    *(uint32_t*)(dstHi + base + 8 * DKH) = hi;
                    *(uint32_t*)(dstLo + base + 8 * DKH) = lo;
                } else {
                    // V transposed: [B,H,DK,S]
                    const size_t base = ((size_t)(b * NH + h) * DKH + dk) * SEQ + srow;
                    const __nv_bfloat16 h0 = __float2bfloat16(v0);
                    const __nv_bfloat16 h1 = __float2bfloat16(v1);
                    const __nv_bfloat16 h2 = __float2bfloat16(v2);
                    const __nv_bfloat16 h3 = __float2bfloat16(v3);
                    dstHi[base]           = h0;
                    dstHi[base + SEQ]     = h1;
                    dstHi[base + 8]       = h2;
                    dstHi[base + SEQ + 8] = h3;
                    dstLo[base]           = __float2bfloat16(v0 - __bfloat162float(h0));
                    dstLo[base + SEQ]     = __float2bfloat16(v1 - __bfloat162float(h1));
                    dstLo[base + 8]       = __float2bfloat16(v2 - __bfloat162float(h2));
                    dstLo[base + SEQ + 8] = __float2bfloat16(v3 - __bfloat162float(h3));
                }
            }
        }
    }
}

__global__ void __launch_bounds__(256, 2)
qkv_mma_kernel(const float* __restrict__ bq, const float* __restrict__ bk,
               const float* __restrict__ bv)
{
    const int z = blockIdx.z;
    const float* B = (z == 0) ? bq : (z == 1) ? bk : bv;
    __nv_bfloat16* Hi = (z == 0) ? g_Qh : (z == 1) ? g_Kh : g_Vth;
    __nv_bfloat16* Lo = (z == 0) ? g_Ql : (z == 1) ? g_Kl : g_Vtl;
    mma_gemm_body(g_Ah + (size_t)z * AMAT, g_Al + (size_t)z * AMAT,
                  g_Wthi + (size_t)z * D_MODEL * D_MODEL,
                  g_Wtlo + (size_t)z * D_MODEL * D_MODEL,
                  B, nullptr, Hi, Lo, (z == 2) ? 2 : 1, blockIdx.x, blockIdx.y);
}

__global__ void __launch_bounds__(256, 2)
out_mma_kernel(const float* __restrict__ bo, float* __restrict__ out)
{
    mma_gemm_body(g_Oh, g_Ol,
                  g_Wthi + (size_t)3 * D_MODEL * D_MODEL,
                  g_Wtlo + (size_t)3 * D_MODEL * D_MODEL,
                  bo, out, nullptr, nullptr, 0, blockIdx.x, blockIdx.y);
}

// ===========================================================================
// Flash attention on mma.sync split-bf16, ldmatrix loads, R10 MMA ordering.
// Output written pre-split (hi/lo) for the out GEMM.
// ===========================================================================
static constexpr int QS = 72;                         // smem row stride (bf16)
static constexpr int FL_Q_BYTES  = 128 * QS * 2;      // 18432
static constexpr int FL_KV_BYTES = 64 * QS * 2;       // 9216
static constexpr int FL_OFF_QH = 0;
static constexpr int FL_OFF_QL = FL_Q_BYTES;
static constexpr int FL_STAGE0 = 2 * FL_Q_BYTES;      // 36864
static constexpr int FL_STAGE  = 4 * FL_KV_BYTES;     // 36864
static constexpr int FLASH_SMEM = FL_STAGE0 + 2 * FL_STAGE;  // 110592

__global__ void __launch_bounds__(256)
flash_mma_kernel()
{
    extern __shared__ char sm[];
    const uint32_t smb = smem_u32(sm);

    const int tid  = threadIdx.x;
    const int lane = tid & 31;
    const int w    = tid >> 5;        // warp 0..7 -> q rows [16w, 16w+16)
    const int r0   = lane >> 2;       // 0..7
    const int cgrp = (lane & 3) * 2;  // 0,2,4,6
    const uint32_t lr  = lane & 7;
    const uint32_t sel = lane >> 3;
    const int qt   = blockIdx.x;      // 0..15
    const int h    = blockIdx.y;
    const int b    = blockIdx.z;

    const size_t bh = ((size_t)(b * NH + h)) * SEQ * DKH;
    const __nv_bfloat16* Qhg = g_Qh + bh + (size_t)qt * 128 * DKH;
    const __nv_bfloat16* Qlg = g_Ql + bh + (size_t)qt * 128 * DKH;
    const __nv_bfloat16* Khg = g_Kh + bh;
    const __nv_bfloat16* Klg = g_Kl + bh;
    const __nv_bfloat16* Vhg = g_Vth + bh;  // [dk][s]
    const __nv_bfloat16* Vlg = g_Vtl + bh;

    auto issueQ = [&] {
#pragma unroll
        for (int i = 0; i < 4; ++i) {
            const int lin = tid + 256 * i;     // 0..1023
            const int row = lin >> 3;          // 0..127
            const int j8  = (lin & 7) * 8;     // 0..56
            const uint32_t so = (uint32_t)(row * QS + j8) * 2;
            cp16(smb + FL_OFF_QH + so, Qhg + (size_t)row * DKH + j8);
            cp16(smb + FL_OFF_QL + so, Qlg + (size_t)row * DKH + j8);
        }
    };
    auto issueKV = [&](int kt) {
        const uint32_t sb = smb + FL_STAGE0 + (kt & 1) * FL_STAGE;
#pragma unroll
        for (int i = 0; i < 2; ++i) {
            const int lin = tid + 256 * i;     // 0..511
            const int row = lin >> 3;          // 0..63
            const int j8  = (lin & 7) * 8;
            const uint32_t so = (uint32_t)(row * QS + j8) * 2;
            cp16(sb + 0 * FL_KV_BYTES + so, Khg + ((size_t)(kt * 64 + row)) * DKH + j8);
            cp16(sb + 1 * FL_KV_BYTES + so, Klg + ((size_t)(kt * 64 + row)) * DKH + j8);
            cp16(sb + 2 * FL_KV_BYTES + so, Vhg + (size_t)row * SEQ + kt * 64 + j8);
            cp16(sb + 3 * FL_KV_BYTES + so, Vlg + (size_t)row * SEQ + kt * 64 + j8);
        }
        CP_COMMIT();
    };

    issueQ();
    issueKV(0);   // group 0 (includes Q)
    issueKV(1);   // group 1

    float m0 = -1e30f, m1 = -1e30f, l0 = 0.0f, l1 = 0.0f;
    float o_acc[8][4];
#pragma unroll
    for (int nf = 0; nf < 8; ++nf)
#pragma unroll
        for (int j = 0; j < 4; ++j) o_acc[nf][j] = 0.0f;

    const float scale = 0.125f;  // 1/sqrt(64)

    // ldmatrix lane offsets (bytes, within a tile of row-stride QS):
    const uint32_t a_lane_off = ((lr + (sel & 1) * 8) * QS + (sel >> 1) * 8) * 2;
    const uint32_t b_lane_off = ((lr + (sel >> 1) * 8) * QS + (sel & 1) * 8) * 2;
    const uint32_t a_base = smb + (uint32_t)(w * 16 * QS) * 2 + a_lane_off;

    for (int kt = 0; kt < 32; ++kt) {
        if (kt < 31) { CP_WAIT1(); } else { CP_WAIT0(); }
        __syncthreads();

        const uint32_t stg = smb + FL_STAGE0 + (kt & 1) * FL_STAGE;

        // ---- S = Q @ K^T (split bf16, 3 MMAs) ---------------------------
        float sacc[8][4];
#pragma unroll
        for (int nf = 0; nf < 8; ++nf)
#pragma unroll
            for (int j = 0; j < 4; ++j) sacc[nf][j] = 0.0f;

#pragma unroll
        for (int kf = 0; kf < 4; ++kf) {
            const uint32_t k0b = (uint32_t)(kf * 16) * 2;
            uint32_t ah[4], al[4];
            ldmx4(ah, a_base + FL_OFF_QH + k0b);
            ldmx4(al, a_base + FL_OFF_QL + k0b);
#pragma unroll
            for (int nfp = 0; nfp < 4; ++nfp) {
                uint32_t bhf[4], blf[4];
                const uint32_t bo = b_lane_off + k0b + (uint32_t)(nfp * 16 * QS) * 2;
                ldmx4(bhf, stg + 0 * FL_KV_BYTES + bo);
                ldmx4(blf, stg + 1 * FL_KV_BYTES + bo);
                mma_bf16(sacc[2 * nfp],     ah, bhf[0], bhf[1]);
                mma_bf16(sacc[2 * nfp],     al, bhf[0], bhf[1]);
                mma_bf16(sacc[2 * nfp],     ah, blf[0], blf[1]);
                mma_bf16(sacc[2 * nfp + 1], ah, bhf[2], bhf[3]);
                mma_bf16(sacc[2 * nfp + 1], al, bhf[2], bhf[3]);
                mma_bf16(sacc[2 * nfp + 1], ah, blf[2], blf[3]);
            }
        }

        // ---- online softmax (rows r0 / r0+8 live in this lane-quad) -----
        float tm0 = sacc[0][0], tm1 = sacc[0][2];
#pragma unroll
        for (int nf = 0; nf < 8; ++nf) {
            tm0 = fmaxf(tm0, fmaxf(sacc[nf][0], sacc[nf][1]));
            tm1 = fmaxf(tm1, fmaxf(sacc[nf][2], sacc[nf][3]));
        }
        tm0 *= scale;
        tm1 *= scale;
#pragma unroll
        for (int d = 1; d < 4; d <<= 1) {
            tm0 = fmaxf(tm0, __shfl_xor_sync(0xffffffffu, tm0, d, 4));
            tm1 = fmaxf(tm1, __shfl_xor_sync(0xffffffffu, tm1, d, 4));
        }
        const float mn0 = fmaxf(m0, tm0);
        const float mn1 = fmaxf(m1, tm1);
        const float cor0 = __expf(m0 - mn0);
        const float cor1 = __expf(m1 - mn1);
        float rs0 = 0.0f, rs1 = 0.0f;
#pragma unroll
        for (int nf = 0; nf < 8; ++nf) {
            sacc[nf][0] = __expf(fmaf(sacc[nf][0], scale, -mn0));
            sacc[nf][1] = __expf(fmaf(sacc[nf][1], scale, -mn0));
            sacc[nf][2] = __expf(fmaf(sacc[nf][2], scale, -mn1));
            sacc[nf][3] = __expf(fmaf(sacc[nf][3], scale, -mn1));
            rs0 += sacc[nf][0] + sacc[nf][1];
            rs1 += sacc[nf][2] + sacc[nf][3];
        }
#pragma unroll
        for (int d = 1; d < 4; d <<= 1) {
            rs0 += __shfl_xor_sync(0xffffffffu, rs0, d, 4);
            rs1 += __shfl_xor_sync(0xffffffffu, rs1, d, 4);
        }
        l0 = l0 * cor0 + rs0;
        l1 = l1 * cor1 + rs1;
#pragma unroll
        for (int nf = 0; nf < 8; ++nf) {
            o_acc[nf][0] *= cor0;
            o_acc[nf][1] *= cor0;
            o_acc[nf][2] *= cor1;
            o_acc[nf][3] *= cor1;
        }
        m0 = mn0;
        m1 = mn1;

        // ---- pack P accumulators -> A fragments (hi + lo residual) ------
        uint32_t pah[4][4], pal[4][4];
#pragma unroll
        for (int kf = 0; kf < 4; ++kf) {
            split2(sacc[2 * kf][0],     sacc[2 * kf][1],     pah[kf][0], pal[kf][0]);
            split2(sacc[2 * kf][2],     sacc[2 * kf][3],     pah[kf][1], pal[kf][1]);
            split2(sacc[2 * kf + 1][0], sacc[2 * kf + 1][1], pah[kf][2], pal[kf][2]);
            split2(sacc[2 * kf + 1][2], sacc[2 * kf + 1][3], pah[kf][3], pal[kf][3]);
        }

        // ---- O += P @ V (V^T in smem: [dk][s]) --------------------------
#pragma unroll
        for (int kf = 0; kf < 4; ++kf) {
            const uint32_t k0b = (uint32_t)(kf * 16) * 2;
#pragma unroll
            for (int nfp = 0; nfp < 4; ++nfp) {
                uint32_t bhf[4], blf[4];
                const uint32_t bo = b_lane_off + k0b + (uint32_t)(nfp * 16 * QS) * 2;
                ldmx4(bhf, stg + 2 * FL_KV_BYTES + bo);
                ldmx4(blf, stg + 3 * FL_KV_BYTES + bo);
                mma_bf16(o_acc[2 * nfp],     pah[kf], bhf[0], bhf[1]);
                mma_bf16(o_acc[2 * nfp],     pal[kf], bhf[0], bhf[1]);
                mma_bf16(o_acc[2 * nfp],     pah[kf], blf[0], blf[1]);
                mma_bf16(o_acc[2 * nfp + 1], pah[kf], bhf[2], bhf[3]);
                mma_bf16(o_acc[2 * nfp + 1], pal[kf], bhf[2], bhf[3]);
                mma_bf16(o_acc[2 * nfp + 1], pah[kf], blf[2], blf[3]);
            }
        }

        __syncthreads();
        if (kt + 2 < 32) issueKV(kt + 2);
    }

    // ---- normalize + write O split bf16 [B, S, H*DK] --------------------
    const float inv0 = 1.0f / l0;
    const float inv1 = 1.0f / l1;
    const int s0 = qt * 128 + w * 16 + r0;
    const size_t obase = ((size_t)b * SEQ) * D_MODEL + h * DKH;
    __nv_bfloat16* OgH = g_Oh + obase;
    __nv_bfloat16* OgL = g_Ol + obase;
#pragma unroll
    for (int nf = 0; nf < 8; ++nf) {
        const int n = nf * 8 + cgrp;
        uint32_t hi, lo;
        split2(o_acc[nf][0] * inv0, o_acc[nf][1] * inv0, hi, lo);
        *(uint32_t*)(OgH + (size_t)s0 * D_MODEL + n) = hi;
        *(uint32_t*)(OgL + (size_t)s0 * D_MODEL + n) = lo;
        split2(o_acc[nf][2] * inv1, o_acc[nf][3] * inv1, hi, lo);
        *(uint32_t*)(OgH + (size_t)(s0 + 8) * D_MODEL + n) = hi;
        *(uint32_t*)(OgL + (size_t)(s0 + 8) * D_MODEL + n) = lo;
    }
}

// ===========================================================================
// Launch
// Inputs: query, key, value, mask, Wq, bq, Wk, bk, Wv, bv, Wo, bo
// ===========================================================================
extern "C" void kernel_launch(void* const* d_in, const int* in_sizes, int n_in,
                              void* d_out, int out_size)
{
    const float* query = (const float*)d_in[0];
    const float* key   = (const float*)d_in[1];
    const float* value = (const float*)d_in[2];
    const float* Wq = (const float*)d_in[4];
    const float* bq = (const float*)d_in[5];
    const float* Wk = (const float*)d_in[6];
    const float* bk = (const float*)d_in[7];
    const float* Wv = (const float*)d_in[8];
    const float* bv = (const float*)d_in[9];
    const float* Wo = (const float*)d_in[10];
    const float* bo = (const float*)d_in[11];

    cudaFuncSetAttribute(flash_mma_kernel,
                         cudaFuncAttributeMaxDynamicSharedMemorySize, FLASH_SMEM);
    cudaFuncSetAttribute(qkv_mma_kernel,
                         cudaFuncAttributeMaxDynamicSharedMemorySize, MMA_SMEM);
    cudaFuncSetAttribute(out_mma_kernel,
                         cudaFuncAttributeMaxDynamicSharedMemorySize, MMA_SMEM);

    asplit_kernel<<<dim3(AMAT / 4 / 256, 3), 256>>>(query, key, value);
    wconv_kernel<<<dim3(32, 32, 4), 256>>>(Wq, Wk, Wv, Wo);

    qkv_mma_kernel<<<dim3(8, 64, 3), 256, MMA_SMEM>>>(bq, bk, bv);

    flash_mma_kernel<<<dim3(SEQ / 128, NH, BATCH), 256, FLASH_SMEM>>>();

    out_mma_kernel<<<dim3(8, 64), 256, MMA_SMEM>>>(bo, (float*)d_out);
}

// round 16
// speedup vs baseline: 1.0427x; 1.0427x over previous
#include <cuda_runtime.h>
#include <cuda_bf16.h>
#include <cstdint>
#include <math.h>

// Problem constants
static constexpr int D_MODEL = 1024;
static constexpr int NH      = 16;
static constexpr int DKH     = 64;
static constexpr int SEQ     = 2048;
static constexpr int BATCH   = 4;
static constexpr int MROWS   = BATCH * SEQ;               // 8192
static constexpr int QKV_ELEMS = BATCH * NH * SEQ * DKH;  // 8388608
static constexpr size_t AMAT = (size_t)MROWS * D_MODEL;   // 8388608

// Scratch (device globals: allocation-free rule)
// Attention output, pre-split for the out GEMM: [B,S,H*DK] bf16 hi/lo
__device__ __nv_bfloat16 g_Oh[AMAT], g_Ol[AMAT];
// Split-bf16 Q/K in [B,H,S,DK]; V transposed in [B,H,DK,S]
__device__ __nv_bfloat16 g_Qh[QKV_ELEMS], g_Ql[QKV_ELEMS];
__device__ __nv_bfloat16 g_Kh[QKV_ELEMS], g_Kl[QKV_ELEMS];
__device__ __nv_bfloat16 g_Vth[QKV_ELEMS], g_Vtl[QKV_ELEMS];
// Pre-transposed + bf16-split weights: Wt[n][k] for each of 4 matrices
__device__ __nv_bfloat16 g_Wthi[4 * D_MODEL * D_MODEL];
__device__ __nv_bfloat16 g_Wtlo[4 * D_MODEL * D_MODEL];

// ===========================================================================
// Helpers (sm_100 base target: mma.sync + cp.async + ldmatrix; NO tcgen05)
// ===========================================================================
__device__ __forceinline__ uint32_t smem_u32(const void* p) {
    uint32_t a;
    asm("{ .reg .u64 t; cvta.to.shared.u64 t, %1; cvt.u32.u64 %0, t; }"
        : "=r"(a) : "l"(p));
    return a;
}

__device__ __forceinline__ void cp16(uint32_t dst, const void* src) {
    asm volatile("cp.async.cg.shared.global [%0], [%1], 16;" :: "r"(dst), "l"(src));
}
#define CP_COMMIT() asm volatile("cp.async.commit_group;" ::: "memory")
#define CP_WAIT0()  asm volatile("cp.async.wait_group 0;" ::: "memory")
#define CP_WAIT1()  asm volatile("cp.async.wait_group 1;" ::: "memory")

// m16n8k16 bf16 MMA, fp32 accumulate
__device__ __forceinline__ void mma_bf16(float* c, const uint32_t* a,
                                         uint32_t b0, uint32_t b1) {
    asm volatile(
        "mma.sync.aligned.m16n8k16.row.col.f32.bf16.bf16.f32 "
        "{%0,%1,%2,%3}, {%4,%5,%6,%7}, {%8,%9}, {%0,%1,%2,%3};"
        : "+f"(c[0]), "+f"(c[1]), "+f"(c[2]), "+f"(c[3])
        : "r"(a[0]), "r"(a[1]), "r"(a[2]), "r"(a[3]), "r"(b0), "r"(b1));
}

// ldmatrix x4: lanes 0-7/8-15/16-23/24-31 address matrices 0/1/2/3
__device__ __forceinline__ void ldmx4(uint32_t* r, uint32_t addr) {
    asm volatile("ldmatrix.sync.aligned.m8n8.x4.shared.b16 {%0,%1,%2,%3}, [%4];"
        : "=r"(r[0]), "=r"(r[1]), "=r"(r[2]), "=r"(r[3]) : "r"(addr));
}

// Fast exp2 (MUFU.EX2)
__device__ __forceinline__ float ex2(float x) {
    float y;
    asm("ex2.approx.f32 %0, %1;" : "=f"(y) : "f"(x));
    return y;
}

__device__ __forceinline__ uint32_t pack_bf16x2(__nv_bfloat16 lo, __nv_bfloat16 hi) {
    return (uint32_t)__bfloat16_as_ushort(lo) |
           ((uint32_t)__bfloat16_as_ushort(hi) << 16);
}

__device__ __forceinline__ void split4(float4 f, uint2& hi, uint2& lo) {
    const __nv_bfloat16 h0 = __float2bfloat16(f.x), h1 = __float2bfloat16(f.y);
    const __nv_bfloat16 h2 = __float2bfloat16(f.z), h3 = __float2bfloat16(f.w);
    hi.x = pack_bf16x2(h0, h1);
    hi.y = pack_bf16x2(h2, h3);
    lo.x = pack_bf16x2(__float2bfloat16(f.x - __bfloat162float(h0)),
                       __float2bfloat16(f.y - __bfloat162float(h1)));
    lo.y = pack_bf16x2(__float2bfloat16(f.z - __bfloat162float(h2)),
                       __float2bfloat16(f.w - __bfloat162float(h3)));
}

// Split two fp32 values into packed hi / packed lo bf16x2
__device__ __forceinline__ void split2(float v0, float v1, uint32_t& hi, uint32_t& lo) {
    const __nv_bfloat16 h0 = __float2bfloat16(v0), h1 = __float2bfloat16(v1);
    hi = pack_bf16x2(h0, h1);
    lo = pack_bf16x2(__float2bfloat16(v0 - __bfloat162float(h0)),
                     __float2bfloat16(v1 - __bfloat162float(h1)));
}

// ===========================================================================
// Weight conversion: W[k][n] fp32  ->  Wt_hi/lo[n][k] bf16 (transposed + split)
// ===========================================================================
__global__ void __launch_bounds__(256)
wconv_kernel(const float* __restrict__ W0, const float* __restrict__ W1,
             const float* __restrict__ W2, const float* __restrict__ W3)
{
    const int z = blockIdx.z;
    const float* W = (z == 0) ? W0 : (z == 1) ? W1 : (z == 2) ? W2 : W3;
    __shared__ float t[32][33];
    const int tx = threadIdx.x & 31;
    const int ty = threadIdx.x >> 5;
    const int kb = blockIdx.y * 32, nb = blockIdx.x * 32;
#pragma unroll
    for (int i = 0; i < 4; ++i)
        t[ty + i * 8][tx] = W[(size_t)(kb + ty + i * 8) * D_MODEL + nb + tx];
    __syncthreads();
    __nv_bfloat16* oh = g_Wthi + (size_t)z * D_MODEL * D_MODEL;
    __nv_bfloat16* ol = g_Wtlo + (size_t)z * D_MODEL * D_MODEL;
#pragma unroll
    for (int i = 0; i < 4; ++i) {
        const int n = nb + ty + i * 8, k = kb + tx;
        const float v = t[tx][ty + i * 8];
        const __nv_bfloat16 h = __float2bfloat16(v);
        oh[(size_t)n * D_MODEL + k] = h;
        ol[(size_t)n * D_MODEL + k] = __float2bfloat16(v - __bfloat162float(h));
    }
}

// ===========================================================================
// Shared GEMM tile constants
// ===========================================================================
static constexpr int SA       = 40;
static constexpr int AB_BYTES = 128 * SA * 2;
static constexpr int OFF_AH = 0;
static constexpr int OFF_AL = AB_BYTES;
static constexpr int OFF_BH = 2 * AB_BYTES;
static constexpr int OFF_BL = 3 * AB_BYTES;
static constexpr int STAGE  = 4 * AB_BYTES;
static constexpr int MMA_SMEM = 2 * STAGE;             // 81920 B

// ===========================================================================
// QKV GEMM: fp32 A with in-loop split (R10-proven), ldmatrix + R10 ordering.
// mode 1: split bf16 -> [B,H,S,DK]; mode 2: split bf16 -> [B,H,DK,S]
// ===========================================================================
__device__ __forceinline__ void mma_gemm_f32A_body(
    const float* __restrict__ Ap,
    const __nv_bfloat16* __restrict__ Wth,
    const __nv_bfloat16* __restrict__ Wtl,
    const float* __restrict__ bias,
    __nv_bfloat16* __restrict__ dstHi, __nv_bfloat16* __restrict__ dstLo,
    int mode, int bx, int by)
{
    extern __shared__ char sm[];
    const uint32_t smb = smem_u32(sm);

    const int tid    = threadIdx.x;
    const int lane   = tid & 31;
    const int wid    = tid >> 5;
    const int warp_m = wid >> 2;
    const int warp_n = wid & 3;
    const int r0     = lane >> 2;
    const int kc     = (lane & 3) * 2;
    const uint32_t lr  = lane & 7;
    const uint32_t sel = lane >> 3;

    const float* Arow = Ap + (size_t)(by * 128) * D_MODEL;
    const __nv_bfloat16* Bh_row = Wth + (size_t)(bx * 128) * D_MODEL;
    const __nv_bfloat16* Bl_row = Wtl + (size_t)(bx * 128) * D_MODEL;

    float acc[4][4][4];
#pragma unroll
    for (int i = 0; i < 4; ++i)
#pragma unroll
        for (int j = 0; j < 4; ++j)
#pragma unroll
            for (int q = 0; q < 4; ++q) acc[i][j][q] = 0.0f;

    auto issue_B = [&](int c, int s) {
        const int k0 = c * 32;
        const uint32_t dh = smb + s * STAGE + OFF_BH;
        const uint32_t dl = smb + s * STAGE + OFF_BL;
#pragma unroll
        for (int i = 0; i < 2; ++i) {
            const int lin = tid + 256 * i;
            const int n   = lin >> 2;
            const int k8  = (lin & 3) * 8;
            const uint32_t so = (uint32_t)(n * SA + k8) * 2;
            cp16(dh + so, Bh_row + (size_t)n * D_MODEL + k0 + k8);
            cp16(dl + so, Bl_row + (size_t)n * D_MODEL + k0 + k8);
        }
        CP_COMMIT();
    };
    auto load_A = [&](int c, float4* fr) {
        const int k0 = c * 32;
#pragma unroll
        for (int i = 0; i < 4; ++i) {
            const int lin = tid + 256 * i;
            const int r   = lin >> 3;
            const int c4  = (lin & 7) * 4;
            fr[i] = *(const float4*)(Arow + (size_t)r * D_MODEL + k0 + c4);
        }
    };
    auto store_A = [&](int s, const float4* fr) {
        char* ah = sm + s * STAGE + OFF_AH;
        char* al = sm + s * STAGE + OFF_AL;
#pragma unroll
        for (int i = 0; i < 4; ++i) {
            const int lin = tid + 256 * i;
            const int r   = lin >> 3;
            const int c4  = (lin & 7) * 4;
            uint2 hi, lo;
            split4(fr[i], hi, lo);
            const uint32_t so = (uint32_t)(r * SA + c4) * 2;
            *(uint2*)(ah + so) = hi;
            *(uint2*)(al + so) = lo;
        }
    };

    {
        issue_B(0, 0);
        float4 fr[4];
        load_A(0, fr);
        store_A(0, fr);
        CP_WAIT0();
        __syncthreads();
    }

    const uint32_t a_lane_off = ((lr + (sel & 1) * 8) * SA + (sel >> 1) * 8) * 2;
    const uint32_t b_lane_off = ((lr + (sel >> 1) * 8) * SA + (sel & 1) * 8) * 2;

    for (int c = 0; c < 32; ++c) {
        const int s = c & 1;
        float4 fr[4];
        if (c + 1 < 32) {
            issue_B(c + 1, s ^ 1);
            load_A(c + 1, fr);
        }

        const uint32_t stg = smb + s * STAGE;

#pragma unroll
        for (int ks = 0; ks < 2; ++ks) {
            const uint32_t k0b = (uint32_t)(ks * 16) * 2;
            uint32_t ah[4][4], al[4][4];
#pragma unroll
            for (int mf = 0; mf < 4; ++mf) {
                const uint32_t ao = a_lane_off + k0b +
                    (uint32_t)((warp_m * 64 + mf * 16) * SA) * 2;
                ldmx4(ah[mf], stg + OFF_AH + ao);
                ldmx4(al[mf], stg + OFF_AL + ao);
            }
#pragma unroll
            for (int nfp = 0; nfp < 2; ++nfp) {
                uint32_t bh[4], bl[4];
                const uint32_t bo = b_lane_off + k0b +
                    (uint32_t)((warp_n * 32 + nfp * 16) * SA) * 2;
                ldmx4(bh, stg + OFF_BH + bo);
                ldmx4(bl, stg + OFF_BL + bo);
#pragma unroll
                for (int mf = 0; mf < 4; ++mf) {
                    mma_bf16(acc[mf][2 * nfp],     ah[mf], bh[0], bh[1]);
                    mma_bf16(acc[mf][2 * nfp],     al[mf], bh[0], bh[1]);
                    mma_bf16(acc[mf][2 * nfp],     ah[mf], bl[0], bl[1]);
                    mma_bf16(acc[mf][2 * nfp + 1], ah[mf], bh[2], bh[3]);
                    mma_bf16(acc[mf][2 * nfp + 1], al[mf], bh[2], bh[3]);
                    mma_bf16(acc[mf][2 * nfp + 1], ah[mf], bl[2], bl[3]);
                }
            }
        }

        if (c + 1 < 32) {
            store_A(s ^ 1, fr);
            CP_WAIT0();
            __syncthreads();
        }
    }

    // ---- epilogue: split bf16 scatter -----------------------------------
#pragma unroll
    for (int mf = 0; mf < 4; ++mf) {
        const int m0 = by * 128 + warp_m * 64 + mf * 16 + r0;
#pragma unroll
        for (int nf = 0; nf < 4; ++nf) {
            const int n = bx * 128 + warp_n * 32 + nf * 8 + kc;
            const float b0 = bias[n], b1 = bias[n + 1];
            const float* c = acc[mf][nf];
            const float v0 = c[0] + b0, v1 = c[1] + b1;
            const float v2 = c[2] + b0, v3 = c[3] + b1;
            const int b = m0 >> 11;
            const int srow = m0 & (SEQ - 1);
            const int h = n >> 6;
            const int dk = n & (DKH - 1);
            if (mode == 1) {
                const size_t base = ((size_t)(b * NH + h) * SEQ + srow) * DKH + dk;
                uint32_t hi, lo;
                split2(v0, v1, hi, lo);
                *(uint32_t*)(dstHi + base) = hi;
                *(uint32_t*)(dstLo + base) = lo;
                split2(v2, v3, hi, lo);
                *(uint32_t*)(dstHi + base + 8 * DKH) = hi;
                *(uint32_t*)(dstLo + base + 8 * DKH) = lo;
            } else {
                // V transposed: [B,H,DK,S]
                const size_t base = ((size_t)(b * NH + h) * DKH + dk) * SEQ + srow;
                const __nv_bfloat16 h0 = __float2bfloat16(v0);
                const __nv_bfloat16 h1 = __float2bfloat16(v1);
                const __nv_bfloat16 h2 = __float2bfloat16(v2);
                const __nv_bfloat16 h3 = __float2bfloat16(v3);
                dstHi[base]           = h0;
                dstHi[base + SEQ]     = h1;
                dstHi[base + 8]       = h2;
                dstHi[base + SEQ + 8] = h3;
                dstLo[base]           = __float2bfloat16(v0 - __bfloat162float(h0));
                dstLo[base + SEQ]     = __float2bfloat16(v1 - __bfloat162float(h1));
                dstLo[base + 8]       = __float2bfloat16(v2 - __bfloat162float(h2));
                dstLo[base + SEQ + 8] = __float2bfloat16(v3 - __bfloat162float(h3));
            }
        }
    }
}

__global__ void __launch_bounds__(256, 2)
qkv_mma_kernel(const float* __restrict__ q, const float* __restrict__ k,
               const float* __restrict__ v,
               const float* __restrict__ bq, const float* __restrict__ bk,
               const float* __restrict__ bv)
{
    const int z = blockIdx.z;
    const float* A = (z == 0) ? q : (z == 1) ? k : v;
    const float* B = (z == 0) ? bq : (z == 1) ? bk : bv;
    __nv_bfloat16* Hi = (z == 0) ? g_Qh : (z == 1) ? g_Kh : g_Vth;
    __nv_bfloat16* Lo = (z == 0) ? g_Ql : (z == 1) ? g_Kl : g_Vtl;
    mma_gemm_f32A_body(A, g_Wthi + (size_t)z * D_MODEL * D_MODEL,
                       g_Wtlo + (size_t)z * D_MODEL * D_MODEL,
                       B, Hi, Lo, (z == 2) ? 2 : 1, blockIdx.x, blockIdx.y);
}

// ===========================================================================
// Out GEMM: pre-split A (g_Oh/g_Ol) streamed via cp.async — no in-loop split.
// ===========================================================================
__global__ void __launch_bounds__(256, 2)
out_mma_kernel(const float* __restrict__ bias, float* __restrict__ out)
{
    extern __shared__ char sm[];
    const uint32_t smb = smem_u32(sm);

    const int bx = blockIdx.x, by = blockIdx.y;
    const int tid    = threadIdx.x;
    const int lane   = tid & 31;
    const int wid    = tid >> 5;
    const int warp_m = wid >> 2;
    const int warp_n = wid & 3;
    const int r0     = lane >> 2;
    const int kc     = (lane & 3) * 2;
    const uint32_t lr  = lane & 7;
    const uint32_t sel = lane >> 3;

    const __nv_bfloat16* Ah_row = g_Oh + (size_t)(by * 128) * D_MODEL;
    const __nv_bfloat16* Al_row = g_Ol + (size_t)(by * 128) * D_MODEL;
    const __nv_bfloat16* Bh_row = g_Wthi + (size_t)3 * D_MODEL * D_MODEL
                                  + (size_t)(bx * 128) * D_MODEL;
    const __nv_bfloat16* Bl_row = g_Wtlo + (size_t)3 * D_MODEL * D_MODEL
                                  + (size_t)(bx * 128) * D_MODEL;

    float acc[4][4][4];
#pragma unroll
    for (int i = 0; i < 4; ++i)
#pragma unroll
        for (int j = 0; j < 4; ++j)
#pragma unroll
            for (int q = 0; q < 4; ++q) acc[i][j][q] = 0.0f;

    auto issue_AB = [&](int c, int s) {
        const int k0 = c * 32;
        const uint32_t sb = smb + s * STAGE;
#pragma unroll
        for (int i = 0; i < 2; ++i) {
            const int lin = tid + 256 * i;
            const int r   = lin >> 2;
            const int k8  = (lin & 3) * 8;
            const uint32_t so = (uint32_t)(r * SA + k8) * 2;
            cp16(sb + OFF_AH + so, Ah_row + (size_t)r * D_MODEL + k0 + k8);
            cp16(sb + OFF_AL + so, Al_row + (size_t)r * D_MODEL + k0 + k8);
            cp16(sb + OFF_BH + so, Bh_row + (size_t)r * D_MODEL + k0 + k8);
            cp16(sb + OFF_BL + so, Bl_row + (size_t)r * D_MODEL + k0 + k8);
        }
        CP_COMMIT();
    };

    issue_AB(0, 0);
    CP_WAIT0();
    __syncthreads();

    const uint32_t a_lane_off = ((lr + (sel & 1) * 8) * SA + (sel >> 1) * 8) * 2;
    const uint32_t b_lane_off = ((lr + (sel >> 1) * 8) * SA + (sel & 1) * 8) * 2;

    for (int c = 0; c < 32; ++c) {
        const int s = c & 1;
        if (c + 1 < 32) issue_AB(c + 1, s ^ 1);

        const uint32_t stg = smb + s * STAGE;

#pragma unroll
        for (int ks = 0; ks < 2; ++ks) {
            const uint32_t k0b = (uint32_t)(ks * 16) * 2;
            uint32_t ah[4][4], al[4][4];
#pragma unroll
            for (int mf = 0; mf < 4; ++mf) {
                const uint32_t ao = a_lane_off + k0b +
                    (uint32_t)((warp_m * 64 + mf * 16) * SA) * 2;
                ldmx4(ah[mf], stg + OFF_AH + ao);
                ldmx4(al[mf], stg + OFF_AL + ao);
            }
#pragma unroll
            for (int nfp = 0; nfp < 2; ++nfp) {
                uint32_t bh[4], bl[4];
                const uint32_t bo = b_lane_off + k0b +
                    (uint32_t)((warp_n * 32 + nfp * 16) * SA) * 2;
                ldmx4(bh, stg + OFF_BH + bo);
                ldmx4(bl, stg + OFF_BL + bo);
#pragma unroll
                for (int mf = 0; mf < 4; ++mf) {
                    mma_bf16(acc[mf][2 * nfp],     ah[mf], bh[0], bh[1]);
                    mma_bf16(acc[mf][2 * nfp],     al[mf], bh[0], bh[1]);
                    mma_bf16(acc[mf][2 * nfp],     ah[mf], bl[0], bl[1]);
                    mma_bf16(acc[mf][2 * nfp + 1], ah[mf], bh[2], bh[3]);
                    mma_bf16(acc[mf][2 * nfp + 1], al[mf], bh[2], bh[3]);
                    mma_bf16(acc[mf][2 * nfp + 1], ah[mf], bl[2], bl[3]);
                }
            }
        }

        if (c + 1 < 32) {
            CP_WAIT0();
            __syncthreads();
        }
    }

    // ---- epilogue: fp32 dense + bias ------------------------------------
#pragma unroll
    for (int mf = 0; mf < 4; ++mf) {
        const int m0 = by * 128 + warp_m * 64 + mf * 16 + r0;
#pragma unroll
        for (int nf = 0; nf < 4; ++nf) {
            const int n = bx * 128 + warp_n * 32 + nf * 8 + kc;
            const float b0 = bias[n], b1 = bias[n + 1];
            const float* c = acc[mf][nf];
            *(float2*)(out + (size_t)m0 * D_MODEL + n) =
                make_float2(c[0] + b0, c[1] + b1);
            *(float2*)(out + (size_t)(m0 + 8) * D_MODEL + n) =
                make_float2(c[2] + b0, c[3] + b1);
        }
    }
}

// ===========================================================================
// Flash attention: mma.sync split-bf16, ldmatrix, R10 ordering, exp2 softmax.
// Output written pre-split (hi/lo). __launch_bounds__(256,2): 2 CTAs/SM.
// ===========================================================================
static constexpr int QS = 72;                         // smem row stride (bf16)
static constexpr int FL_Q_BYTES  = 128 * QS * 2;      // 18432
static constexpr int FL_KV_BYTES = 64 * QS * 2;       // 9216
static constexpr int FL_OFF_QH = 0;
static constexpr int FL_OFF_QL = FL_Q_BYTES;
static constexpr int FL_STAGE0 = 2 * FL_Q_BYTES;      // 36864
static constexpr int FL_STAGE  = 4 * FL_KV_BYTES;     // 36864
static constexpr int FLASH_SMEM = FL_STAGE0 + 2 * FL_STAGE;  // 110592

__global__ void __launch_bounds__(256, 2)
flash_mma_kernel()
{
    extern __shared__ char sm[];
    const uint32_t smb = smem_u32(sm);

    const int tid  = threadIdx.x;
    const int lane = tid & 31;
    const int w    = tid >> 5;        // warp 0..7 -> q rows [16w, 16w+16)
    const int r0   = lane >> 2;       // 0..7
    const int cgrp = (lane & 3) * 2;  // 0,2,4,6
    const uint32_t lr  = lane & 7;
    const uint32_t sel = lane >> 3;
    const int qt   = blockIdx.x;      // 0..15
    const int h    = blockIdx.y;
    const int b    = blockIdx.z;

    const size_t bh = ((size_t)(b * NH + h)) * SEQ * DKH;
    const __nv_bfloat16* Qhg = g_Qh + bh + (size_t)qt * 128 * DKH;
    const __nv_bfloat16* Qlg = g_Ql + bh + (size_t)qt * 128 * DKH;
    const __nv_bfloat16* Khg = g_Kh + bh;
    const __nv_bfloat16* Klg = g_Kl + bh;
    const __nv_bfloat16* Vhg = g_Vth + bh;  // [dk][s]
    const __nv_bfloat16* Vlg = g_Vtl + bh;

    auto issueQ = [&] {
#pragma unroll
        for (int i = 0; i < 4; ++i) {
            const int lin = tid + 256 * i;     // 0..1023
            const int row = lin >> 3;          // 0..127
            const int j8  = (lin & 7) * 8;     // 0..56
            const uint32_t so = (uint32_t)(row * QS + j8) * 2;
            cp16(smb + FL_OFF_QH + so, Qhg + (size_t)row * DKH + j8);
            cp16(smb + FL_OFF_QL + so, Qlg + (size_t)row * DKH + j8);
        }
    };
    auto issueKV = [&](int kt) {
        const uint32_t sb = smb + FL_STAGE0 + (kt & 1) * FL_STAGE;
#pragma unroll
        for (int i = 0; i < 2; ++i) {
            const int lin = tid + 256 * i;     // 0..511
            const int row = lin >> 3;          // 0..63
            const int j8  = (lin & 7) * 8;
            const uint32_t so = (uint32_t)(row * QS + j8) * 2;
            cp16(sb + 0 * FL_KV_BYTES + so, Khg + ((size_t)(kt * 64 + row)) * DKH + j8);
            cp16(sb + 1 * FL_KV_BYTES + so, Klg + ((size_t)(kt * 64 + row)) * DKH + j8);
            cp16(sb + 2 * FL_KV_BYTES + so, Vhg + (size_t)row * SEQ + kt * 64 + j8);
            cp16(sb + 3 * FL_KV_BYTES + so, Vlg + (size_t)row * SEQ + kt * 64 + j8);
        }
        CP_COMMIT();
    };

    issueQ();
    issueKV(0);   // group 0 (includes Q)
    issueKV(1);   // group 1

    float m0 = -1e30f, m1 = -1e30f, l0 = 0.0f, l1 = 0.0f;
    float o_acc[8][4];
#pragma unroll
    for (int nf = 0; nf < 8; ++nf)
#pragma unroll
        for (int j = 0; j < 4; ++j) o_acc[nf][j] = 0.0f;

    // exp2-domain softmax: scale2 = (1/sqrt(64)) * log2(e)
    const float scale2 = 0.125f * 1.44269504088896f;

    const uint32_t a_lane_off = ((lr + (sel & 1) * 8) * QS + (sel >> 1) * 8) * 2;
    const uint32_t b_lane_off = ((lr + (sel >> 1) * 8) * QS + (sel & 1) * 8) * 2;
    const uint32_t a_base = smb + (uint32_t)(w * 16 * QS) * 2 + a_lane_off;

    for (int kt = 0; kt < 32; ++kt) {
        if (kt < 31) { CP_WAIT1(); } else { CP_WAIT0(); }
        __syncthreads();

        const uint32_t stg = smb + FL_STAGE0 + (kt & 1) * FL_STAGE;

        // ---- S = Q @ K^T (split bf16, 3 MMAs) ---------------------------
        float sacc[8][4];
#pragma unroll
        for (int nf = 0; nf < 8; ++nf)
#pragma unroll
            for (int j = 0; j < 4; ++j) sacc[nf][j] = 0.0f;

#pragma unroll
        for (int kf = 0; kf < 4; ++kf) {
            const uint32_t k0b = (uint32_t)(kf * 16) * 2;
            uint32_t ah[4], al[4];
            ldmx4(ah, a_base + FL_OFF_QH + k0b);
            ldmx4(al, a_base + FL_OFF_QL + k0b);
#pragma unroll
            for (int nfp = 0; nfp < 4; ++nfp) {
                uint32_t bhf[4], blf[4];
                const uint32_t bo = b_lane_off + k0b + (uint32_t)(nfp * 16 * QS) * 2;
                ldmx4(bhf, stg + 0 * FL_KV_BYTES + bo);
                ldmx4(blf, stg + 1 * FL_KV_BYTES + bo);
                mma_bf16(sacc[2 * nfp],     ah, bhf[0], bhf[1]);
                mma_bf16(sacc[2 * nfp],     al, bhf[0], bhf[1]);
                mma_bf16(sacc[2 * nfp],     ah, blf[0], blf[1]);
                mma_bf16(sacc[2 * nfp + 1], ah, bhf[2], bhf[3]);
                mma_bf16(sacc[2 * nfp + 1], al, bhf[2], bhf[3]);
                mma_bf16(sacc[2 * nfp + 1], ah, blf[2], blf[3]);
            }
        }

        // ---- online softmax in exp2 domain ------------------------------
        float tm0 = sacc[0][0], tm1 = sacc[0][2];
#pragma unroll
        for (int nf = 0; nf < 8; ++nf) {
            tm0 = fmaxf(tm0, fmaxf(sacc[nf][0], sacc[nf][1]));
            tm1 = fmaxf(tm1, fmaxf(sacc[nf][2], sacc[nf][3]));
        }
        tm0 *= scale2;
        tm1 *= scale2;
#pragma unroll
        for (int d = 1; d < 4; d <<= 1) {
            tm0 = fmaxf(tm0, __shfl_xor_sync(0xffffffffu, tm0, d, 4));
            tm1 = fmaxf(tm1, __shfl_xor_sync(0xffffffffu, tm1, d, 4));
        }
        const float mn0 = fmaxf(m0, tm0);
        const float mn1 = fmaxf(m1, tm1);
        const float cor0 = ex2(m0 - mn0);
        const float cor1 = ex2(m1 - mn1);
        float rs0 = 0.0f, rs1 = 0.0f;
#pragma unroll
        for (int nf = 0; nf < 8; ++nf) {
            sacc[nf][0] = ex2(fmaf(sacc[nf][0], scale2, -mn0));
            sacc[nf][1] = ex2(fmaf(sacc[nf][1], scale2, -mn0));
            sacc[nf][2] = ex2(fmaf(sacc[nf][2], scale2, -mn1));
            sacc[nf][3] = ex2(fmaf(sacc[nf][3], scale2, -mn1));
            rs0 += sacc[nf][0] + sacc[nf][1];
            rs1 += sacc[nf][2] + sacc[nf][3];
        }
#pragma unroll
        for (int d = 1; d < 4; d <<= 1) {
            rs0 += __shfl_xor_sync(0xffffffffu, rs0, d, 4);
            rs1 += __shfl_xor_sync(0xffffffffu, rs1, d, 4);
        }
        l0 = l0 * cor0 + rs0;
        l1 = l1 * cor1 + rs1;
#pragma unroll
        for (int nf = 0; nf < 8; ++nf) {
            o_acc[nf][0] *= cor0;
            o_acc[nf][1] *= cor0;
            o_acc[nf][2] *= cor1;
            o_acc[nf][3] *= cor1;
        }
        m0 = mn0;
        m1 = mn1;

        // ---- pack P accumulators -> A fragments (hi + lo residual) ------
        uint32_t pah[4][4], pal[4][4];
#pragma unroll
        for (int kf = 0; kf < 4; ++kf) {
            split2(sacc[2 * kf][0],     sacc[2 * kf][1],     pah[kf][0], pal[kf][0]);
            split2(sacc[2 * kf][2],     sacc[2 * kf][3],     pah[kf][1], pal[kf][1]);
            split2(sacc[2 * kf + 1][0], sacc[2 * kf + 1][1], pah[kf][2], pal[kf][2]);
            split2(sacc[2 * kf + 1][2], sacc[2 * kf + 1][3], pah[kf][3], pal[kf][3]);
        }

        // ---- O += P @ V (V^T in smem: [dk][s]) --------------------------
#pragma unroll
        for (int kf = 0; kf < 4; ++kf) {
            const uint32_t k0b = (uint32_t)(kf * 16) * 2;
#pragma unroll
            for (int nfp = 0; nfp < 4; ++nfp) {
                uint32_t bhf[4], blf[4];
                const uint32_t bo = b_lane_off + k0b + (uint32_t)(nfp * 16 * QS) * 2;
                ldmx4(bhf, stg + 2 * FL_KV_BYTES + bo);
                ldmx4(blf, stg + 3 * FL_KV_BYTES + bo);
                mma_bf16(o_acc[2 * nfp],     pah[kf], bhf[0], bhf[1]);
                mma_bf16(o_acc[2 * nfp],     pal[kf], bhf[0], bhf[1]);
                mma_bf16(o_acc[2 * nfp],     pah[kf], blf[0], blf[1]);
                mma_bf16(o_acc[2 * nfp + 1], pah[kf], bhf[2], bhf[3]);
                mma_bf16(o_acc[2 * nfp + 1], pal[kf], bhf[2], bhf[3]);
                mma_bf16(o_acc[2 * nfp + 1], pah[kf], blf[2], blf[3]);
            }
        }

        __syncthreads();
        if (kt + 2 < 32) issueKV(kt + 2);
    }

    // ---- normalize + write O split bf16 [B, S, H*DK] --------------------
    const float inv0 = 1.0f / l0;
    const float inv1 = 1.0f / l1;
    const int s0 = qt * 128 + w * 16 + r0;
    const size_t obase = ((size_t)b * SEQ) * D_MODEL + h * DKH;
    __nv_bfloat16* OgH = g_Oh + obase;
    __nv_bfloat16* OgL = g_Ol + obase;
#pragma unroll
    for (int nf = 0; nf < 8; ++nf) {
        const int n = nf * 8 + cgrp;
        uint32_t hi, lo;
        split2(o_acc[nf][0] * inv0, o_acc[nf][1] * inv0, hi, lo);
        *(uint32_t*)(OgH + (size_t)s0 * D_MODEL + n) = hi;
        *(uint32_t*)(OgL + (size_t)s0 * D_MODEL + n) = lo;
        split2(o_acc[nf][2] * inv1, o_acc[nf][3] * inv1, hi, lo);
        *(uint32_t*)(OgH + (size_t)(s0 + 8) * D_MODEL + n) = hi;
        *(uint32_t*)(OgL + (size_t)(s0 + 8) * D_MODEL + n) = lo;
    }
}

// ===========================================================================
// Launch
// Inputs: query, key, value, mask, Wq, bq, Wk, bk, Wv, bv, Wo, bo
// ===========================================================================
extern "C" void kernel_launch(void* const* d_in, const int* in_sizes, int n_in,
                              void* d_out, int out_size)
{
    const float* query = (const float*)d_in[0];
    const float* key   = (const float*)d_in[1];
    const float* value = (const float*)d_in[2];
    const float* Wq = (const float*)d_in[4];
    const float* bq = (const float*)d_in[5];
    const float* Wk = (const float*)d_in[6];
    const float* bk = (const float*)d_in[7];
    const float* Wv = (const float*)d_in[8];
    const float* bv = (const float*)d_in[9];
    const float* Wo = (const float*)d_in[10];
    const float* bo = (const float*)d_in[11];

    cudaFuncSetAttribute(flash_mma_kernel,
                         cudaFuncAttributeMaxDynamicSharedMemorySize, FLASH_SMEM);
    cudaFuncSetAttribute(qkv_mma_kernel,
                         cudaFuncAttributeMaxDynamicSharedMemorySize, MMA_SMEM);
    cudaFuncSetAttribute(out_mma_kernel,
                         cudaFuncAttributeMaxDynamicSharedMemorySize, MMA_SMEM);

    wconv_kernel<<<dim3(32, 32, 4), 256>>>(Wq, Wk, Wv, Wo);

    qkv_mma_kernel<<<dim3(8, 64, 3), 256, MMA_SMEM>>>(query, key, value, bq, bk, bv);

    flash_mma_kernel<<<dim3(SEQ / 128, NH, BATCH), 256, FLASH_SMEM>>>();

    out_mma_kernel<<<dim3(8, 64), 256, MMA_SMEM>>>(bo, (float*)d_out);
}